// round 2
// baseline (speedup 1.0000x reference)
#include <cuda_runtime.h>
#include <math.h>

#define N_NODES_MAX 100000
#define E_MAX       3200000
#define IN_DIM      128
#define HID         32

// ---- scratch (static device memory: allocation-free) ----
__device__ int   g_is64;                      // 1 if edge_index is int64, 0 if int32
__device__ int   g_src[E_MAX];
__device__ int   g_dst[E_MAX];
__device__ int   g_deg[N_NODES_MAX];
__device__ float g_dinv[N_NODES_MAX];
__device__ __align__(16) float g_hs  [N_NODES_MAX * HID];  // (x@W1)*dinv[node]
__device__ __align__(16) float g_acc1[N_NODES_MAX * HID];  // layer-1 accumulator
__device__ float g_gs  [N_NODES_MAX];         // (relu(acc1+b1).W2)*dinv[node]
__device__ float g_acc2[N_NODES_MAX];         // layer-2 accumulator

// 0) detect edge dtype: int64 view of int32 data combines two random indices
//    -> value >= 2^32 with overwhelming probability over 64 samples.
__global__ void k_detect(const void* __restrict__ ei, int n) {
    if (threadIdx.x == 0 && blockIdx.x == 0) {
        const long long* p = (const long long*)ei;
        int is64 = 1;
        for (int i = 0; i < 64; i++) {
            long long v = p[i];
            if (v < 0 || v >= (long long)n) { is64 = 0; break; }
        }
        g_is64 = is64;
    }
}

// 1) deg[i] = 1 (self-loop)
__global__ void k_init_deg(int n) {
    int i = blockIdx.x * blockDim.x + threadIdx.x;
    if (i < n) g_deg[i] = 1;
}

// 2) edge conversion (dtype-branching) + in-degree histogram on dst
__global__ void k_convert_deg(const void* __restrict__ ei, int E) {
    int e = blockIdx.x * blockDim.x + threadIdx.x;
    if (e >= E) return;
    int s, d;
    if (g_is64) {
        const long long* p = (const long long*)ei;
        s = (int)p[e];
        d = (int)p[(long long)E + e];
    } else {
        const int* p = (const int*)ei;
        s = p[e];
        d = p[E + e];
    }
    g_src[e] = s;
    g_dst[e] = d;
    atomicAdd(&g_deg[d], 1);
}

// 3) dinv = rsqrt(deg)
__global__ void k_dinv(int n) {
    int i = blockIdx.x * blockDim.x + threadIdx.x;
    if (i < n) g_dinv[i] = rsqrtf((float)g_deg[i]);
}

// 4) hs = (x @ W1) * dinv[node]; acc1 init = hs * dinv (self-loop term)
//    warp-per-node, W1 in smem, x row broadcast via shfl
__global__ void k_xw(const float* __restrict__ x, const float* __restrict__ W1, int n) {
    __shared__ float Ws[IN_DIM * HID];
    int tid = threadIdx.x;
    for (int i = tid; i < IN_DIM * HID; i += blockDim.x) Ws[i] = W1[i];
    __syncthreads();
    int warp = tid >> 5, lane = tid & 31;
    int node = blockIdx.x * (blockDim.x >> 5) + warp;
    if (node >= n) return;
    const float4* xr = (const float4*)(x + (size_t)node * IN_DIM);
    float4 xv = xr[lane];  // lane holds x[4*lane .. 4*lane+3]
    float acc = 0.f;
#pragma unroll
    for (int sl = 0; sl < 32; sl++) {
        float a0 = __shfl_sync(0xffffffffu, xv.x, sl);
        float a1 = __shfl_sync(0xffffffffu, xv.y, sl);
        float a2 = __shfl_sync(0xffffffffu, xv.z, sl);
        float a3 = __shfl_sync(0xffffffffu, xv.w, sl);
        int k = sl * 4;
        acc = fmaf(a0, Ws[(k + 0) * HID + lane], acc);
        acc = fmaf(a1, Ws[(k + 1) * HID + lane], acc);
        acc = fmaf(a2, Ws[(k + 2) * HID + lane], acc);
        acc = fmaf(a3, Ws[(k + 3) * HID + lane], acc);
    }
    float di = g_dinv[node];
    float hsv = acc * di;
    g_hs  [node * HID + lane] = hsv;
    g_acc1[node * HID + lane] = hsv * di;   // self-loop: h * dinv^2
}

// 5) layer-1 edge scatter: 8 threads per edge, float4 per thread,
//    vectorized no-return reduction into acc1[dst]
__global__ void k_scatter1(int E) {
    int t = blockIdx.x * blockDim.x + threadIdx.x;
    int e = t >> 3;
    if (e >= E) return;
    int fg = (t & 7) << 2;
    int s = g_src[e];
    int d = g_dst[e];
    float nd = g_dinv[d];
    float4 v = *(const float4*)&g_hs[s * HID + fg];
    float* p = &g_acc1[d * HID + fg];
    asm volatile("red.global.add.v4.f32 [%0], {%1, %2, %3, %4};"
                 :: "l"(p), "f"(v.x * nd), "f"(v.y * nd), "f"(v.z * nd), "f"(v.w * nd)
                 : "memory");
}

// 6) finish layer 1 + transform for layer 2:
//    g = relu(acc1 + b1) . W2 ;  gs = g*dinv ; acc2 init = gs*dinv (self-loop)
__global__ void k_finish1(const float* __restrict__ b1, const float* __restrict__ W2, int n) {
    int gt = blockIdx.x * blockDim.x + threadIdx.x;
    int node = gt >> 5;
    int lane = threadIdx.x & 31;
    if (node >= n) return;
    float v = g_acc1[node * HID + lane] + b1[lane];
    v = fmaxf(v, 0.f);
    float p = v * W2[lane];
#pragma unroll
    for (int o = 16; o > 0; o >>= 1) p += __shfl_xor_sync(0xffffffffu, p, o);
    if (lane == 0) {
        float di  = g_dinv[node];
        float gsv = p * di;
        g_gs  [node] = gsv;
        g_acc2[node] = gsv * di;  // self-loop
    }
}

// 7) layer-2 edge scatter: scalar no-return reduction
__global__ void k_scatter2(int E) {
    int e = blockIdx.x * blockDim.x + threadIdx.x;
    if (e >= E) return;
    int s = g_src[e];
    int d = g_dst[e];
    float v = g_gs[s] * g_dinv[d];
    asm volatile("red.global.add.f32 [%0], %1;" :: "l"(&g_acc2[d]), "f"(v) : "memory");
}

// 8) out = sigmoid(acc2 + b2)
__global__ void k_out(float* __restrict__ out, const float* __restrict__ b2, int n) {
    int i = blockIdx.x * blockDim.x + threadIdx.x;
    if (i >= n) return;
    float z = g_acc2[i] + b2[0];
    out[i] = 1.f / (1.f + __expf(-z));
}

extern "C" void kernel_launch(void* const* d_in, const int* in_sizes, int n_in,
                              void* d_out, int out_size) {
    // ---- robust input identification by element count ----
    const float* x  = nullptr;
    const void*  ei = nullptr;
    const float* W1 = nullptr;
    const float* b1 = nullptr;
    const float* W2 = nullptr;
    const float* b2 = nullptr;
    long long ei_elems = 0;
    int n32_seen = 0;
    for (int i = 0; i < n_in; i++) {
        long long sz = in_sizes[i];
        if (sz == (long long)N_NODES_MAX * IN_DIM)      x  = (const float*)d_in[i];
        else if (sz == 2LL * E_MAX)                     { ei = d_in[i]; ei_elems = sz; }
        else if (sz == (long long)IN_DIM * HID)         W1 = (const float*)d_in[i];
        else if (sz == HID) { if (n32_seen++ == 0) b1 = (const float*)d_in[i];
                              else                 W2 = (const float*)d_in[i]; }
        else if (sz == 1)                               b2 = (const float*)d_in[i];
    }
    // fallback to declared order if anything missing
    if (!x || !ei || !W1 || !b1 || !W2 || !b2) {
        x  = (const float*)d_in[0];
        ei = d_in[1];                 ei_elems = in_sizes[1];
        W1 = (const float*)d_in[2];
        b1 = (const float*)d_in[3];
        W2 = (const float*)d_in[4];
        b2 = (const float*)d_in[5];
    }
    float* out = (float*)d_out;

    int n = out_size;
    int E = (int)(ei_elems / 2);
    if (n > N_NODES_MAX) n = N_NODES_MAX;
    if (E > E_MAX)       E = E_MAX;

    const int TPB = 256;

    k_detect     <<<1, 32>>>(ei, n);
    k_init_deg   <<<(n + TPB - 1) / TPB, TPB>>>(n);
    k_convert_deg<<<(E + TPB - 1) / TPB, TPB>>>(ei, E);
    k_dinv       <<<(n + TPB - 1) / TPB, TPB>>>(n);
    // warp-per-node matmul: 8 nodes per 256-thread block
    k_xw         <<<(n + 7) / 8, TPB>>>(x, W1, n);
    // 8 threads per edge
    {
        long long tot = (long long)E * 8;
        k_scatter1<<<(unsigned)((tot + TPB - 1) / TPB), TPB>>>(E);
    }
    k_finish1    <<<(n * 32 + TPB - 1) / TPB, TPB>>>(b1, W2, n);
    k_scatter2   <<<(E + TPB - 1) / TPB, TPB>>>(E);
    k_out        <<<(n + TPB - 1) / TPB, TPB>>>(out, b2, n);
}